// round 7
// baseline (speedup 1.0000x reference)
#include <cuda_runtime.h>
#include <cuda_fp16.h>
#include <cstdint>

// ---------------- problem constants ----------------
#define Bsz   2
#define Tseq  1024
#define NQH   32
#define NKV   8
#define Dh    128
#define BM    64         // query rows per CTA
#define BN    64         // key rows per tile
#define NTHREADS 256     // 4 consumer warps + 4 producer warps
#define LOG2E 1.4426950408889634f
#define MINIT (-1.0e30f) // |MINIT*LOG2E| < FLT_MAX (NaN-safe)

// ---------------- smem layout (bytes) ----------------
// QHI/QLO staging: persistent (consumers read fragments once)
// BUF b: KHI(16K) | KLO(16K) | VHI(16K), double buffered
#define OFF_QHI  0
#define OFF_QLO  16384
#define OFF_BUF  32768
#define BUFSZ    49152
#define KLO_OFF  16384
#define VHI_OFF  32768
#define OFF_SEG  (OFF_BUF + 2 * BUFSZ)     // 131072
#define SMEM_TOTAL (OFF_SEG + 512)

// named barriers: FULL0=1, FULL1=2, EMPTY0=3, EMPTY1=4 (count = 256)
#define NB_SYNC(id)   asm volatile("bar.sync %0, 256;"   :: "r"(id) : "memory")
#define NB_ARRIVE(id) asm volatile("bar.arrive %0, 256;" :: "r"(id) : "memory")

__device__ __forceinline__ uint32_t smem_u32(const void* p) {
    uint32_t a;
    asm("{ .reg .u64 t; cvta.to.shared.u64 t, %1; cvt.u32.u64 %0, t; }"
        : "=r"(a) : "l"(p));
    return a;
}

// swizzled byte offset of 16B chunk (row, c) in a 256B-row tile
__device__ __forceinline__ uint32_t toff(int row, int c) {
    return ((uint32_t)row << 8) + (((uint32_t)(c ^ (row & 7))) << 4);
}

__device__ __forceinline__ void ldsm4(uint32_t* r, uint32_t a) {
    asm volatile("ldmatrix.sync.aligned.m8n8.x4.shared.b16 {%0,%1,%2,%3}, [%4];"
                 : "=r"(r[0]), "=r"(r[1]), "=r"(r[2]), "=r"(r[3]) : "r"(a));
}
__device__ __forceinline__ void ldsm4t(uint32_t* r, uint32_t a) {
    asm volatile("ldmatrix.sync.aligned.m8n8.x4.trans.shared.b16 {%0,%1,%2,%3}, [%4];"
                 : "=r"(r[0]), "=r"(r[1]), "=r"(r[2]), "=r"(r[3]) : "r"(a));
}
__device__ __forceinline__ void mma16816(float* d, const uint32_t* a, const uint32_t* b) {
    asm volatile("mma.sync.aligned.m16n8k16.row.col.f32.f16.f16.f32 "
                 "{%0,%1,%2,%3}, {%4,%5,%6,%7}, {%8,%9}, {%0,%1,%2,%3};"
                 : "+f"(d[0]), "+f"(d[1]), "+f"(d[2]), "+f"(d[3])
                 : "r"(a[0]), "r"(a[1]), "r"(a[2]), "r"(a[3]),
                   "r"(b[0]), "r"(b[1]));
}

__device__ __forceinline__ uint32_t pack_h2(float lo, float hi) {
    uint32_t r;
    asm("cvt.rn.f16x2.f32 %0, %1, %2;" : "=r"(r) : "f"(hi), "f"(lo));
    return r;
}
__device__ __forceinline__ uint32_t ex2_h2(uint32_t x) {
    uint32_t r;
    asm("ex2.approx.f16x2 %0, %1;" : "=r"(r) : "r"(x));
    return r;
}

__device__ __forceinline__ void split2(float x, float y, uint32_t& h, uint32_t& l) {
    __half hx = __float2half_rn(x), hy = __float2half_rn(y);
    __half lx = __float2half_rn(x - __half2float(hx));
    __half ly = __float2half_rn(y - __half2float(hy));
    __half2 hh = __halves2half2(hx, hy);
    __half2 ll = __halves2half2(lx, ly);
    h = *(uint32_t*)&hh;
    l = *(uint32_t*)&ll;
}

__device__ __forceinline__ void cvt_sts8(uint32_t ahi, uint32_t alo, const float* v) {
    uint32_t h[4], l[4];
    #pragma unroll
    for (int i = 0; i < 4; i++)
        split2(v[2*i], v[2*i+1], h[i], l[i]);
    asm volatile("st.shared.v4.b32 [%0], {%1,%2,%3,%4};"
                 :: "r"(ahi), "r"(h[0]), "r"(h[1]), "r"(h[2]), "r"(h[3]) : "memory");
    asm volatile("st.shared.v4.b32 [%0], {%1,%2,%3,%4};"
                 :: "r"(alo), "r"(l[0]), "r"(l[1]), "r"(l[2]), "r"(l[3]) : "memory");
}
__device__ __forceinline__ void cvt_sts4(uint32_t ahi, const float* v) {
    uint32_t h[4];
    #pragma unroll
    for (int i = 0; i < 4; i++)
        h[i] = pack_h2(v[2*i], v[2*i+1]);
    asm volatile("st.shared.v4.b32 [%0], {%1,%2,%3,%4};"
                 :: "r"(ahi), "r"(h[0]), "r"(h[1]), "r"(h[2]), "r"(h[3]) : "memory");
}

// producer helpers: 128 threads (ptid 0..127)
__device__ __forceinline__ void load_K(const float* __restrict__ Kg,
                                       const int* __restrict__ seg,
                                       uint32_t kbase, int* sSegDst,
                                       int b, int k0, int kh, int ptid)
{
    #pragma unroll
    for (int it = 0; it < 8; it++) {
        int idx = ptid + it * 128;
        int r = idx >> 4, c = idx & 15;
        const float* g = Kg + ((size_t)((b * Tseq + k0 + r) * NKV + kh)) * Dh + c * 8;
        float4 v0 = *(const float4*)g;
        float4 v1 = *(const float4*)(g + 4);
        float arr[8] = { v0.x, v0.y, v0.z, v0.w, v1.x, v1.y, v1.z, v1.w };
        uint32_t o = toff(r, c);
        cvt_sts8(kbase + o, kbase + KLO_OFF + o, arr);
    }
    if (ptid < BN) sSegDst[ptid] = seg[b * Tseq + k0 + ptid];
}

__device__ __forceinline__ void load_V(const float* __restrict__ Vg,
                                       uint32_t vbase,
                                       int b, int k0, int kh, int ptid)
{
    #pragma unroll
    for (int it = 0; it < 8; it++) {
        int idx = ptid + it * 128;
        int r = idx >> 4, c = idx & 15;
        const float* g = Vg + ((size_t)((b * Tseq + k0 + r) * NKV + kh)) * Dh + c * 8;
        float4 v0 = *(const float4*)g;
        float4 v1 = *(const float4*)(g + 4);
        float arr[8] = { v0.x, v0.y, v0.z, v0.w, v1.x, v1.y, v1.z, v1.w };
        cvt_sts4(vbase + toff(r, c), arr);
    }
}

__global__ __launch_bounds__(NTHREADS, 1)
void attn_ws_kernel(const float* __restrict__ Q,
                    const float* __restrict__ K,
                    const float* __restrict__ V,
                    const int*   __restrict__ seg,
                    float*       __restrict__ Out)
{
    extern __shared__ char smem[];
    const uint32_t sb = smem_u32(smem);
    const int tid  = threadIdx.x;
    const int wid  = tid >> 5;          // 0..3 consumers, 4..7 producers
    const int lane = tid & 31;

    const int qtile = blockIdx.x;
    const int h     = blockIdx.y;
    const int b     = blockIdx.z;
    const int kh    = h >> 2;
    const int q0    = qtile * BM;

    // ---- Q prologue: all 256 threads stage Q hi/lo into smem ----
    #pragma unroll
    for (int it = 0; it < 4; it++) {
        int idx = tid + it * NTHREADS;
        int r = idx >> 4, c = idx & 15;
        const float* g = Q + ((size_t)((b * Tseq + q0 + r) * NQH + h)) * Dh + c * 8;
        float4 v0 = *(const float4*)g;
        float4 v1 = *(const float4*)(g + 4);
        float arr[8] = { v0.x, v0.y, v0.z, v0.w, v1.x, v1.y, v1.z, v1.w };
        uint32_t o = toff(r, c);
        cvt_sts8(sb + OFF_QHI + o, sb + OFF_QLO + o, arr);
    }
    __syncthreads();

    const int sqmin = seg[b * Tseq + q0];
    const int sqmax = seg[b * Tseq + q0 + BM - 1];
    const int ktmax = qtile;
    auto inactive = [&](int t) -> bool {
        int s0 = seg[b * Tseq + t * BN];
        int s1 = seg[b * Tseq + t * BN + BN - 1];
        return (s1 < sqmin) | (s0 > sqmax);
    };
    int kt0 = 0;
    while (kt0 < ktmax && inactive(kt0)) kt0++;   // diagonal always active

    if (wid >= 4) {
        // ================= PRODUCER =================
        const int ptid = tid - 128;
        int fill = 0;
        int kt = kt0;
        while (kt <= ktmax) {
            const int buf = fill & 1;
            if (fill >= 2) NB_SYNC(3 + buf);       // wait consumers done with buf
            const uint32_t base = sb + OFF_BUF + buf * BUFSZ;
            load_K(K, seg, base, (int*)(smem + OFF_SEG + buf * 256), b, kt * BN, kh, ptid);
            load_V(V, base + VHI_OFF, b, kt * BN, kh, ptid);
            __threadfence_block();                 // STS visible before arrive
            NB_ARRIVE(1 + buf);                    // signal FULL
            fill++;
            kt++;
            while (kt <= ktmax && inactive(kt)) kt++;
        }
        return;
    }

    // ================= CONSUMER =================
    const int quad = lane >> 2;
    const int qr   = lane & 3;
    const int rowl0 = 16 * wid + quad;
    const int row0  = q0 + rowl0;
    const int sq0 = seg[b * Tseq + row0];
    const int sq1 = seg[b * Tseq + row0 + 8];

    // ldmatrix addressing
    const int rA    = 16 * wid + (lane & 15);
    const uint32_t aoff_base = (uint32_t)rA << 8;
    const int aswz   = rA & 7;
    const int achunk = lane >> 4;
    const int brow_l = ((lane >> 4) << 3) + (lane & 7);
    const int bsel   = (lane >> 3) & 1;
    const int bswz   = lane & 7;
    const int vrow_l = lane & 15;
    const int vsel   = lane >> 4;

    // persistent Q hi/lo fragments (staging never overwritten)
    uint32_t Qh[8][4], Ql[8][4];
    #pragma unroll
    for (int k = 0; k < 8; k++) {
        uint32_t ao = aoff_base + ((uint32_t)(((k << 1) + achunk) ^ aswz) << 4);
        ldsm4(Qh[k], sb + OFF_QHI + ao);
        ldsm4(Ql[k], sb + OFF_QLO + ao);
    }

    float m0 = MINIT, m1 = MINIT, l0 = 0.0f, l1 = 0.0f;
    float Oa[16][4];
    #pragma unroll
    for (int i = 0; i < 16; i++)
        #pragma unroll
        for (int j = 0; j < 4; j++) Oa[i][j] = 0.0f;

    const float NEG = -__int_as_float(0x7f800000);   // -inf
    const uint32_t ONES2[2] = { 0x3C003C00u, 0x3C003C00u };

    int cons = 0;
    int kt = kt0;
    while (kt <= ktmax) {
        const int buf = cons & 1;
        const int k0 = kt * BN;
        NB_SYNC(1 + buf);                          // wait FULL
        const uint32_t cbase = sb + OFF_BUF + buf * BUFSZ;
        int* segCur = (int*)(smem + OFF_SEG + buf * 256);

        // ---- QK: S = qh*kh + qh*kl + ql*kh ----
        float S[8][4];
        #pragma unroll
        for (int n = 0; n < 8; n++)
            #pragma unroll
            for (int j = 0; j < 4; j++) S[n][j] = 0.0f;

        #pragma unroll
        for (int k = 0; k < 8; k++) {
            #pragma unroll
            for (int np = 0; np < 4; np++) {
                uint32_t bh[4], bl[4];
                uint32_t bo = ((uint32_t)(np * 16 + brow_l) << 8)
                            + ((uint32_t)(((k << 1) + bsel) ^ bswz) << 4);
                ldsm4(bh, cbase + bo);
                ldsm4(bl, cbase + KLO_OFF + bo);
                mma16816(S[2*np],   Qh[k], bh);
                mma16816(S[2*np+1], Qh[k], bh + 2);
                mma16816(S[2*np],   Qh[k], bl);
                mma16816(S[2*np+1], Qh[k], bl + 2);
                mma16816(S[2*np],   Ql[k], bh);
                mma16816(S[2*np+1], Ql[k], bh + 2);
            }
        }

        // ---- masking + row max ----
        float mx0 = m0, mx1 = m1;
        #pragma unroll
        for (int n = 0; n < 8; n++) {
            int cc = n * 8 + qr * 2;
            int cg = k0 + cc;
            int sk0 = segCur[cc], sk1 = segCur[cc + 1];
            bool a00 = (sk0 == sq0) && (cg     <= row0);
            bool a01 = (sk1 == sq0) && (cg + 1 <= row0);
            bool a10 = (sk0 == sq1) && (cg     <= row0 + 8);
            bool a11 = (sk1 == sq1) && (cg + 1 <= row0 + 8);
            S[n][0] = a00 ? S[n][0] : NEG;
            S[n][1] = a01 ? S[n][1] : NEG;
            S[n][2] = a10 ? S[n][2] : NEG;
            S[n][3] = a11 ? S[n][3] : NEG;
            mx0 = fmaxf(mx0, fmaxf(S[n][0], S[n][1]));
            mx1 = fmaxf(mx1, fmaxf(S[n][2], S[n][3]));
        }
        mx0 = fmaxf(mx0, __shfl_xor_sync(0xffffffffu, mx0, 1));
        mx0 = fmaxf(mx0, __shfl_xor_sync(0xffffffffu, mx0, 2));
        mx1 = fmaxf(mx1, __shfl_xor_sync(0xffffffffu, mx1, 1));
        mx1 = fmaxf(mx1, __shfl_xor_sync(0xffffffffu, mx1, 2));

        float sc0 = __expf(m0 - mx0);
        float sc1 = __expf(m1 - mx1);
        m0 = mx0; m1 = mx1;

        // ---- exp2 in fp16x2: P fragments directly ----
        const float c0 = -mx0 * LOG2E;
        const float c1 = -mx1 * LOG2E;
        uint32_t PH[4][4];
        #pragma unroll
        for (int n = 0; n < 8; n++) {
            float t0 = fmaf(S[n][0], LOG2E, c0);
            float t1 = fmaf(S[n][1], LOG2E, c0);
            float t2 = fmaf(S[n][2], LOG2E, c1);
            float t3 = fmaf(S[n][3], LOG2E, c1);
            uint32_t p01 = ex2_h2(pack_h2(t0, t1));
            uint32_t p23 = ex2_h2(pack_h2(t2, t3));
            PH[n >> 1][(n & 1) << 1]       = p01;
            PH[n >> 1][((n & 1) << 1) | 1] = p23;
        }

        // ---- row sums via ones-MMA ----
        float Lacc[4] = { 0.0f, 0.0f, 0.0f, 0.0f };
        #pragma unroll
        for (int kc = 0; kc < 4; kc++)
            mma16816(Lacc, PH[kc], ONES2);
        l0 = l0 * sc0 + Lacc[0];
        l1 = l1 * sc1 + Lacc[2];

        // ---- rescale O ----
        #pragma unroll
        for (int nd = 0; nd < 16; nd++) {
            Oa[nd][0] *= sc0; Oa[nd][1] *= sc0;
            Oa[nd][2] *= sc1; Oa[nd][3] *= sc1;
        }

        // ---- PV ----
        #pragma unroll
        for (int kc = 0; kc < 4; kc++) {
            #pragma unroll
            for (int ndp = 0; ndp < 8; ndp++) {
                uint32_t vh[4];
                uint32_t vo = ((uint32_t)(kc * 16 + vrow_l) << 8)
                            + ((uint32_t)((2 * ndp + vsel) ^ bswz) << 4);
                ldsm4t(vh, cbase + VHI_OFF + vo);
                mma16816(Oa[2*ndp],   PH[kc], vh);
                mma16816(Oa[2*ndp+1], PH[kc], vh + 2);
            }
        }

        NB_ARRIVE(3 + buf);                        // signal EMPTY
        cons++;
        kt++;
        while (kt <= ktmax && inactive(kt)) kt++;
    }

    // ---- epilogue ----
    const float inv0 = 1.0f / l0;
    const float inv1 = 1.0f / l1;
    float* o0 = Out + ((size_t)((b * Tseq + row0) * NQH + h)) * Dh;
    float* o1 = Out + ((size_t)((b * Tseq + row0 + 8) * NQH + h)) * Dh;
    #pragma unroll
    for (int nd = 0; nd < 16; nd++) {
        int d = nd * 8 + qr * 2;
        float2 w0 = make_float2(Oa[nd][0] * inv0, Oa[nd][1] * inv0);
        float2 w1 = make_float2(Oa[nd][2] * inv1, Oa[nd][3] * inv1);
        *(float2*)(o0 + d) = w0;
        *(float2*)(o1 + d) = w1;
    }
}

extern "C" void kernel_launch(void* const* d_in, const int* in_sizes, int n_in,
                              void* d_out, int out_size)
{
    const float* Q   = (const float*)d_in[0];
    const float* K   = (const float*)d_in[1];
    const float* V   = (const float*)d_in[2];
    const int*   seg = (const int*)d_in[3];
    float*       O   = (float*)d_out;

    cudaFuncSetAttribute(attn_ws_kernel,
                         cudaFuncAttributeMaxDynamicSharedMemorySize, SMEM_TOTAL);

    dim3 grid(Tseq / BM, NQH, Bsz);
    attn_ws_kernel<<<grid, NTHREADS, SMEM_TOTAL>>>(Q, K, V, seg, O);
}

// round 8
// speedup vs baseline: 1.2950x; 1.2950x over previous
#include <cuda_runtime.h>
#include <cuda_fp16.h>
#include <cstdint>

// ---------------- problem constants ----------------
#define Bsz   2
#define Tseq  1024
#define NQH   32
#define NKV   8
#define Dh    128
#define BM    64
#define BN    64
#define NTHREADS 128
#define LOG2E 1.4426950408889634f
#define MINIT (-1.0e30f)   // |MINIT*LOG2E| < FLT_MAX (NaN-safe)

// ---------------- pre-converted K/V blob (global scratch) ----------------
// per (b, kh, kt): KHI(16K) | KLO(16K) | VHI(16K), swizzled tile layout
#define KLO_OFF  16384
#define VHI_OFF  32768
#define BLOBSZ   49152
__device__ __align__(16) static char GKV[(size_t)Bsz * NKV * 16 * BLOBSZ];

// ---------------- smem layout ----------------
#define OFF_BUF0 0
#define OFF_BUF1 49152
#define OFF_SEG  98304            // 2 x 256B seg rows
#define SMEM_TOTAL (OFF_SEG + 512)   // 98,816 B -> 2 CTAs/SM

__device__ __forceinline__ uint32_t smem_u32(const void* p) {
    uint32_t a;
    asm("{ .reg .u64 t; cvta.to.shared.u64 t, %1; cvt.u32.u64 %0, t; }"
        : "=r"(a) : "l"(p));
    return a;
}
__device__ __forceinline__ uint32_t toff(int row, int c) {
    return ((uint32_t)row << 8) + (((uint32_t)(c ^ (row & 7))) << 4);
}
__device__ __forceinline__ void ldsm4(uint32_t* r, uint32_t a) {
    asm volatile("ldmatrix.sync.aligned.m8n8.x4.shared.b16 {%0,%1,%2,%3}, [%4];"
                 : "=r"(r[0]), "=r"(r[1]), "=r"(r[2]), "=r"(r[3]) : "r"(a));
}
__device__ __forceinline__ void ldsm4t(uint32_t* r, uint32_t a) {
    asm volatile("ldmatrix.sync.aligned.m8n8.x4.trans.shared.b16 {%0,%1,%2,%3}, [%4];"
                 : "=r"(r[0]), "=r"(r[1]), "=r"(r[2]), "=r"(r[3]) : "r"(a));
}
__device__ __forceinline__ void mma16816(float* d, const uint32_t* a, const uint32_t* b) {
    asm volatile("mma.sync.aligned.m16n8k16.row.col.f32.f16.f16.f32 "
                 "{%0,%1,%2,%3}, {%4,%5,%6,%7}, {%8,%9}, {%0,%1,%2,%3};"
                 : "+f"(d[0]), "+f"(d[1]), "+f"(d[2]), "+f"(d[3])
                 : "r"(a[0]), "r"(a[1]), "r"(a[2]), "r"(a[3]),
                   "r"(b[0]), "r"(b[1]));
}
__device__ __forceinline__ uint32_t pack_h2(float lo, float hi) {
    uint32_t r;
    asm("cvt.rn.f16x2.f32 %0, %1, %2;" : "=r"(r) : "f"(hi), "f"(lo));
    return r;
}
__device__ __forceinline__ uint32_t ex2_h2(uint32_t x) {
    uint32_t r;
    asm("ex2.approx.f16x2 %0, %1;" : "=r"(r) : "r"(x));
    return r;
}
__device__ __forceinline__ void split2(float x, float y, uint32_t& h, uint32_t& l) {
    __half hx = __float2half_rn(x), hy = __float2half_rn(y);
    __half lx = __float2half_rn(x - __half2float(hx));
    __half ly = __float2half_rn(y - __half2float(hy));
    __half2 hh = __halves2half2(hx, hy);
    __half2 ll = __halves2half2(lx, ly);
    h = *(uint32_t*)&hh;
    l = *(uint32_t*)&ll;
}
__device__ __forceinline__ void cvt_sts8(uint32_t ahi, uint32_t alo, const float* v) {
    uint32_t h[4], l[4];
    #pragma unroll
    for (int i = 0; i < 4; i++)
        split2(v[2*i], v[2*i+1], h[i], l[i]);
    asm volatile("st.shared.v4.b32 [%0], {%1,%2,%3,%4};"
                 :: "r"(ahi), "r"(h[0]), "r"(h[1]), "r"(h[2]), "r"(h[3]) : "memory");
    asm volatile("st.shared.v4.b32 [%0], {%1,%2,%3,%4};"
                 :: "r"(alo), "r"(l[0]), "r"(l[1]), "r"(l[2]), "r"(l[3]) : "memory");
}

#define CP16(sa, gp) \
    asm volatile("cp.async.cg.shared.global [%0], [%1], 16;" \
                 :: "r"(sa), "l"(gp) : "memory")
#define CP_COMMIT() asm volatile("cp.async.commit_group;" ::: "memory")
#define CP_WAIT1()  asm volatile("cp.async.wait_group 1;"  ::: "memory")

// ============ kernel 1: convert K,V -> fp16 hi/lo swizzled blobs ============
__global__ __launch_bounds__(512)
void convert_kv(const float* __restrict__ K, const float* __restrict__ V)
{
    const int kt = blockIdx.x, kh = blockIdx.y, b = blockIdx.z;
    const int tid = threadIdx.x;
    char* blob = GKV + ((size_t)((b * NKV + kh) * 16 + kt)) * BLOBSZ;

    #pragma unroll
    for (int it = 0; it < 2; it++) {
        int idx = tid + it * 512;
        int r = idx >> 4, c = idx & 15;
        uint32_t o = toff(r, c);
        {
            const float* g = K + ((size_t)((b * Tseq + kt * BN + r) * NKV + kh)) * Dh + c * 8;
            float4 v0 = *(const float4*)g;
            float4 v1 = *(const float4*)(g + 4);
            float arr[8] = { v0.x, v0.y, v0.z, v0.w, v1.x, v1.y, v1.z, v1.w };
            uint32_t h[4], l[4];
            #pragma unroll
            for (int i = 0; i < 4; i++)
                split2(arr[2*i], arr[2*i+1], h[i], l[i]);
            *(uint4*)(blob + o)           = make_uint4(h[0], h[1], h[2], h[3]);
            *(uint4*)(blob + KLO_OFF + o) = make_uint4(l[0], l[1], l[2], l[3]);
        }
        {
            const float* g = V + ((size_t)((b * Tseq + kt * BN + r) * NKV + kh)) * Dh + c * 8;
            float4 v0 = *(const float4*)g;
            float4 v1 = *(const float4*)(g + 4);
            uint32_t h[4];
            h[0] = pack_h2(v0.x, v0.y); h[1] = pack_h2(v0.z, v0.w);
            h[2] = pack_h2(v1.x, v1.y); h[3] = pack_h2(v1.z, v1.w);
            *(uint4*)(blob + VHI_OFF + o) = make_uint4(h[0], h[1], h[2], h[3]);
        }
    }
}

// ============ kernel 2: attention ============
__global__ __launch_bounds__(NTHREADS, 2)
void attn_hmma_kernel(const float* __restrict__ Q,
                      const int*   __restrict__ seg,
                      float*       __restrict__ Out)
{
    extern __shared__ char smem[];
    const uint32_t sb = smem_u32(smem);
    const int tid  = threadIdx.x;
    const int wid  = tid >> 5;
    const int lane = tid & 31;
    const int quad = lane >> 2;
    const int qr   = lane & 3;

    const int qtile = blockIdx.x;
    const int h     = blockIdx.y;
    const int b     = blockIdx.z;
    const int kh    = h >> 2;
    const int q0    = qtile * BM;

    // ---- prologue: Q -> fp16 hi/lo staged in BUF0 ----
    #pragma unroll
    for (int it = 0; it < 8; it++) {
        int idx = tid + it * NTHREADS;
        int r = idx >> 4, c = idx & 15;
        const float* g = Q + ((size_t)((b * Tseq + q0 + r) * NQH + h)) * Dh + c * 8;
        float4 v0 = *(const float4*)g;
        float4 v1 = *(const float4*)(g + 4);
        float arr[8] = { v0.x, v0.y, v0.z, v0.w, v1.x, v1.y, v1.z, v1.w };
        uint32_t o = toff(r, c);
        cvt_sts8(sb + OFF_BUF0 + o, sb + OFF_BUF0 + KLO_OFF + o, arr);
    }
    __syncthreads();

    // fragment addressing
    const int rA    = 16 * wid + (lane & 15);
    const uint32_t aoff_base = (uint32_t)rA << 8;
    const int aswz   = rA & 7;
    const int achunk = lane >> 4;
    const int brow_l = ((lane >> 4) << 3) + (lane & 7);
    const int bsel   = (lane >> 3) & 1;
    const int bswz   = lane & 7;
    const int vrow_l = lane & 15;
    const int vsel   = lane >> 4;

    // persistent Q hi/lo fragments
    uint32_t Qh[8][4], Ql[8][4];
    #pragma unroll
    for (int k = 0; k < 8; k++) {
        uint32_t ao = aoff_base + ((uint32_t)(((k << 1) + achunk) ^ aswz) << 4);
        ldsm4(Qh[k], sb + OFF_BUF0 + ao);
        ldsm4(Ql[k], sb + OFF_BUF0 + KLO_OFF + ao);
    }
    __syncthreads();   // staging reads done; BUF0 reusable

    const int rowl0 = 16 * wid + quad;
    const int row0  = q0 + rowl0;
    const int sq0 = seg[b * Tseq + row0];
    const int sq1 = seg[b * Tseq + row0 + 8];
    const int sqmin = seg[b * Tseq + q0];
    const int sqmax = seg[b * Tseq + q0 + BM - 1];

    const int ktmax = qtile;
    auto inactive = [&](int t) -> bool {
        int s0 = seg[b * Tseq + t * BN];
        int s1 = seg[b * Tseq + t * BN + BN - 1];
        return (s1 < sqmin) | (s0 > sqmax);
    };

    const char* blobs = GKV + ((size_t)(b * NKV + kh) * 16) * BLOBSZ;
    auto issue_tile = [&](int t, int buf) {
        const char* gsrc = blobs + (size_t)t * BLOBSZ;
        uint32_t sdst = sb + (buf ? OFF_BUF1 : OFF_BUF0);
        #pragma unroll
        for (int it = 0; it < 24; it++) {
            uint32_t off = (uint32_t)tid * 16 + (uint32_t)it * 2048;
            CP16(sdst + off, gsrc + off);
        }
        if (tid < 16)
            CP16(sb + OFF_SEG + buf * 256 + tid * 16,
                 (const char*)(seg + b * Tseq + t * BN) + tid * 16);
    };

    int cur = 0;
    while (cur < ktmax && inactive(cur)) cur++;     // diagonal always active
    int nxt = cur + 1;
    while (nxt <= ktmax && inactive(nxt)) nxt++;

    // prologue pipeline: slot0 -> buf0, slot1 -> buf1 (commit even if empty)
    issue_tile(cur, 0);
    CP_COMMIT();
    if (nxt <= ktmax) issue_tile(nxt, 1);
    CP_COMMIT();

    float m0 = MINIT, m1 = MINIT, l0 = 0.0f, l1 = 0.0f;
    float Oa[16][4];
    #pragma unroll
    for (int i = 0; i < 16; i++)
        #pragma unroll
        for (int j = 0; j < 4; j++) Oa[i][j] = 0.0f;

    const float NEG = -__int_as_float(0x7f800000);   // -inf
    const uint32_t ONES2[2] = { 0x3C003C00u, 0x3C003C00u };
    int it8 = 0;

    while (cur <= ktmax) {
        const int buf = it8 & 1;
        const int k0 = cur * BN;
        CP_WAIT1();
        __syncthreads();                          // tile 'cur' resident
        const uint32_t cbase = sb + (buf ? OFF_BUF1 : OFF_BUF0);
        const int* segCur = (const int*)(smem + OFF_SEG + buf * 256);

        // ---- QK: S = qh*kh + qh*kl + ql*kh ----
        float S[8][4];
        #pragma unroll
        for (int n = 0; n < 8; n++)
            #pragma unroll
            for (int j = 0; j < 4; j++) S[n][j] = 0.0f;

        #pragma unroll
        for (int k = 0; k < 8; k++) {
            #pragma unroll
            for (int np = 0; np < 4; np++) {
                uint32_t bh[4], bl[4];
                uint32_t bo = ((uint32_t)(np * 16 + brow_l) << 8)
                            + ((uint32_t)(((k << 1) + bsel) ^ bswz) << 4);
                ldsm4(bh, cbase + bo);
                ldsm4(bl, cbase + KLO_OFF + bo);
                mma16816(S[2*np],   Qh[k], bh);
                mma16816(S[2*np+1], Qh[k], bh + 2);
                mma16816(S[2*np],   Qh[k], bl);
                mma16816(S[2*np+1], Qh[k], bl + 2);
                mma16816(S[2*np],   Ql[k], bh);
                mma16816(S[2*np+1], Ql[k], bh + 2);
            }
        }

        // ---- masking + row max ----
        float mx0 = m0, mx1 = m1;
        #pragma unroll
        for (int n = 0; n < 8; n++) {
            int cc = n * 8 + qr * 2;
            int cg = k0 + cc;
            int sk0 = segCur[cc], sk1 = segCur[cc + 1];
            bool a00 = (sk0 == sq0) && (cg     <= row0);
            bool a01 = (sk1 == sq0) && (cg + 1 <= row0);
            bool a10 = (sk0 == sq1) && (cg     <= row0 + 8);
            bool a11 = (sk1 == sq1) && (cg + 1 <= row0 + 8);
            S[n][0] = a00 ? S[n][0] : NEG;
            S[n][1] = a01 ? S[n][1] : NEG;
            S[n][2] = a10 ? S[n][2] : NEG;
            S[n][3] = a11 ? S[n][3] : NEG;
            mx0 = fmaxf(mx0, fmaxf(S[n][0], S[n][1]));
            mx1 = fmaxf(mx1, fmaxf(S[n][2], S[n][3]));
        }
        mx0 = fmaxf(mx0, __shfl_xor_sync(0xffffffffu, mx0, 1));
        mx0 = fmaxf(mx0, __shfl_xor_sync(0xffffffffu, mx0, 2));
        mx1 = fmaxf(mx1, __shfl_xor_sync(0xffffffffu, mx1, 1));
        mx1 = fmaxf(mx1, __shfl_xor_sync(0xffffffffu, mx1, 2));

        float sc0 = __expf(m0 - mx0);
        float sc1 = __expf(m1 - mx1);
        m0 = mx0; m1 = mx1;

        // ---- exp2 fp16x2 -> P fragments ----
        const float c0 = -mx0 * LOG2E;
        const float c1 = -mx1 * LOG2E;
        uint32_t PH[4][4];
        #pragma unroll
        for (int n = 0; n < 8; n++) {
            float t0 = fmaf(S[n][0], LOG2E, c0);
            float t1 = fmaf(S[n][1], LOG2E, c0);
            float t2 = fmaf(S[n][2], LOG2E, c1);
            float t3 = fmaf(S[n][3], LOG2E, c1);
            uint32_t p01 = ex2_h2(pack_h2(t0, t1));
            uint32_t p23 = ex2_h2(pack_h2(t2, t3));
            PH[n >> 1][(n & 1) << 1]       = p01;
            PH[n >> 1][((n & 1) << 1) | 1] = p23;
        }

        // ---- row sums via ones-MMA ----
        float Lacc[4] = { 0.0f, 0.0f, 0.0f, 0.0f };
        #pragma unroll
        for (int kc = 0; kc < 4; kc++)
            mma16816(Lacc, PH[kc], ONES2);
        l0 = l0 * sc0 + Lacc[0];
        l1 = l1 * sc1 + Lacc[2];

        // ---- rescale O ----
        #pragma unroll
        for (int nd = 0; nd < 16; nd++) {
            Oa[nd][0] *= sc0; Oa[nd][1] *= sc0;
            Oa[nd][2] *= sc1; Oa[nd][3] *= sc1;
        }

        // ---- PV ----
        #pragma unroll
        for (int kc = 0; kc < 4; kc++) {
            #pragma unroll
            for (int ndp = 0; ndp < 8; ndp++) {
                uint32_t vh[4];
                uint32_t vo = ((uint32_t)(kc * 16 + vrow_l) << 8)
                            + ((uint32_t)((2 * ndp + vsel) ^ bswz) << 4);
                ldsm4t(vh, cbase + VHI_OFF + vo);
                mma16816(Oa[2*ndp],   PH[kc], vh);
                mma16816(Oa[2*ndp+1], PH[kc], vh + 2);
            }
        }

        __syncthreads();                           // all reads of buf done
        int n2 = nxt + 1;
        while (n2 <= ktmax && inactive(n2)) n2++;
        if (n2 <= ktmax) issue_tile(n2, buf);
        CP_COMMIT();                               // one group per slot, always

        cur = nxt; nxt = n2; it8++;
    }

    // ---- epilogue ----
    const float inv0 = 1.0f / l0;
    const float inv1 = 1.0f / l1;
    float* o0 = Out + ((size_t)((b * Tseq + row0) * NQH + h)) * Dh;
    float* o1 = Out + ((size_t)((b * Tseq + row0 + 8) * NQH + h)) * Dh;
    #pragma unroll
    for (int nd = 0; nd < 16; nd++) {
        int d = nd * 8 + qr * 2;
        float2 w0 = make_float2(Oa[nd][0] * inv0, Oa[nd][1] * inv0);
        float2 w1 = make_float2(Oa[nd][2] * inv1, Oa[nd][3] * inv1);
        *(float2*)(o0 + d) = w0;
        *(float2*)(o1 + d) = w1;
    }
}

extern "C" void kernel_launch(void* const* d_in, const int* in_sizes, int n_in,
                              void* d_out, int out_size)
{
    const float* Q   = (const float*)d_in[0];
    const float* K   = (const float*)d_in[1];
    const float* V   = (const float*)d_in[2];
    const int*   seg = (const int*)d_in[3];
    float*       O   = (float*)d_out;

    dim3 cg(16, NKV, Bsz);
    convert_kv<<<cg, 512>>>(K, V);

    cudaFuncSetAttribute(attn_hmma_kernel,
                         cudaFuncAttributeMaxDynamicSharedMemorySize, SMEM_TOTAL);
    dim3 grid(Tseq / BM, NQH, Bsz);
    attn_hmma_kernel<<<grid, NTHREADS, SMEM_TOTAL>>>(Q, seg, O);
}

// round 9
// speedup vs baseline: 1.2994x; 1.0034x over previous
#include <cuda_runtime.h>
#include <cuda_fp16.h>
#include <cstdint>

// ---------------- problem constants ----------------
#define Bsz   2
#define Tseq  1024
#define NQH   32
#define NKV   8
#define Dh    128
#define BM    64
#define BN    64
#define NQT   (Tseq / BM)     // 16
#define NTHREADS 128
#define LOG2E 1.4426950408889634f
#define MINIT (-1.0e30f)      // |MINIT*LOG2E| < FLT_MAX (NaN-safe)

// ---------------- pre-converted K/V blob (global scratch) ----------------
// per (b, kh, kt): KHI(16K) | KLO(16K) | VHI(16K), swizzled tile layout
#define KLO_OFF  16384
#define VHI_OFF  32768
#define BLOBSZ   49152
__device__ __align__(16) static char GKV[(size_t)Bsz * NKV * NQT * BLOBSZ];

// ---------------- smem layout ----------------
#define OFF_BUF0 0
#define OFF_BUF1 49152
#define SMEM_TOTAL (2 * 49152)   // 98,304 B -> 2 CTAs/SM

__device__ __forceinline__ uint32_t smem_u32(const void* p) {
    uint32_t a;
    asm("{ .reg .u64 t; cvta.to.shared.u64 t, %1; cvt.u32.u64 %0, t; }"
        : "=r"(a) : "l"(p));
    return a;
}
__device__ __forceinline__ uint32_t toff(int row, int c) {
    return ((uint32_t)row << 8) + (((uint32_t)(c ^ (row & 7))) << 4);
}
__device__ __forceinline__ void ldsm4(uint32_t* r, uint32_t a) {
    asm volatile("ldmatrix.sync.aligned.m8n8.x4.shared.b16 {%0,%1,%2,%3}, [%4];"
                 : "=r"(r[0]), "=r"(r[1]), "=r"(r[2]), "=r"(r[3]) : "r"(a));
}
__device__ __forceinline__ void ldsm4t(uint32_t* r, uint32_t a) {
    asm volatile("ldmatrix.sync.aligned.m8n8.x4.trans.shared.b16 {%0,%1,%2,%3}, [%4];"
                 : "=r"(r[0]), "=r"(r[1]), "=r"(r[2]), "=r"(r[3]) : "r"(a));
}
__device__ __forceinline__ void mma16816(float* d, const uint32_t* a, const uint32_t* b) {
    asm volatile("mma.sync.aligned.m16n8k16.row.col.f32.f16.f16.f32 "
                 "{%0,%1,%2,%3}, {%4,%5,%6,%7}, {%8,%9}, {%0,%1,%2,%3};"
                 : "+f"(d[0]), "+f"(d[1]), "+f"(d[2]), "+f"(d[3])
                 : "r"(a[0]), "r"(a[1]), "r"(a[2]), "r"(a[3]),
                   "r"(b[0]), "r"(b[1]));
}
__device__ __forceinline__ uint32_t pack_h2(float lo, float hi) {
    uint32_t r;
    asm("cvt.rn.f16x2.f32 %0, %1, %2;" : "=r"(r) : "f"(hi), "f"(lo));
    return r;
}
__device__ __forceinline__ uint32_t ex2_h2(uint32_t x) {
    uint32_t r;
    asm("ex2.approx.f16x2 %0, %1;" : "=r"(r) : "r"(x));
    return r;
}
__device__ __forceinline__ void split2(float x, float y, uint32_t& h, uint32_t& l) {
    __half hx = __float2half_rn(x), hy = __float2half_rn(y);
    __half lx = __float2half_rn(x - __half2float(hx));
    __half ly = __float2half_rn(y - __half2float(hy));
    __half2 hh = __halves2half2(hx, hy);
    __half2 ll = __halves2half2(lx, ly);
    h = *(uint32_t*)&hh;
    l = *(uint32_t*)&ll;
}
__device__ __forceinline__ void cvt_sts8(uint32_t ahi, uint32_t alo, const float* v) {
    uint32_t h[4], l[4];
    #pragma unroll
    for (int i = 0; i < 4; i++)
        split2(v[2*i], v[2*i+1], h[i], l[i]);
    asm volatile("st.shared.v4.b32 [%0], {%1,%2,%3,%4};"
                 :: "r"(ahi), "r"(h[0]), "r"(h[1]), "r"(h[2]), "r"(h[3]) : "memory");
    asm volatile("st.shared.v4.b32 [%0], {%1,%2,%3,%4};"
                 :: "r"(alo), "r"(l[0]), "r"(l[1]), "r"(l[2]), "r"(l[3]) : "memory");
}

#define CP16(sa, gp) \
    asm volatile("cp.async.cg.shared.global [%0], [%1], 16;" \
                 :: "r"(sa), "l"(gp) : "memory")
#define CP_COMMIT() asm volatile("cp.async.commit_group;" ::: "memory")
#define CP_WAIT1()  asm volatile("cp.async.wait_group 1;"  ::: "memory")

// first index in [0, r] whose seg equals seg[r] (seg ascending within batch)
__device__ __forceinline__ int seg_start(const int* __restrict__ seg, int base, int r) {
    const int sv = seg[base + r];
    int lo = 0, hi = r;
    while (lo < hi) {
        int mid = (lo + hi) >> 1;
        if (seg[base + mid] == sv) hi = mid; else lo = mid + 1;
    }
    return lo;
}

// ============ kernel 1: convert K,V -> fp16 hi/lo swizzled blobs ============
__global__ __launch_bounds__(512)
void convert_kv(const float* __restrict__ K, const float* __restrict__ V)
{
    const int kt = blockIdx.x, kh = blockIdx.y, b = blockIdx.z;
    const int tid = threadIdx.x;
    char* blob = GKV + ((size_t)((b * NKV + kh) * NQT + kt)) * BLOBSZ;

    #pragma unroll
    for (int it = 0; it < 2; it++) {
        int idx = tid + it * 512;
        int r = idx >> 4, c = idx & 15;
        uint32_t o = toff(r, c);
        {
            const float* g = K + ((size_t)((b * Tseq + kt * BN + r) * NKV + kh)) * Dh + c * 8;
            float4 v0 = *(const float4*)g;
            float4 v1 = *(const float4*)(g + 4);
            float arr[8] = { v0.x, v0.y, v0.z, v0.w, v1.x, v1.y, v1.z, v1.w };
            uint32_t h[4], l[4];
            #pragma unroll
            for (int i = 0; i < 4; i++)
                split2(arr[2*i], arr[2*i+1], h[i], l[i]);
            *(uint4*)(blob + o)           = make_uint4(h[0], h[1], h[2], h[3]);
            *(uint4*)(blob + KLO_OFF + o) = make_uint4(l[0], l[1], l[2], l[3]);
        }
        {
            const float* g = V + ((size_t)((b * Tseq + kt * BN + r) * NKV + kh)) * Dh + c * 8;
            float4 v0 = *(const float4*)g;
            float4 v1 = *(const float4*)(g + 4);
            uint32_t h[4];
            h[0] = pack_h2(v0.x, v0.y); h[1] = pack_h2(v0.z, v0.w);
            h[2] = pack_h2(v1.x, v1.y); h[3] = pack_h2(v1.z, v1.w);
            *(uint4*)(blob + VHI_OFF + o) = make_uint4(h[0], h[1], h[2], h[3]);
        }
    }
}

// ============ kernel 2: attention ============
__global__ __launch_bounds__(NTHREADS, 2)
void attn_hmma_kernel(const float* __restrict__ Q,
                      const int*   __restrict__ seg,
                      float*       __restrict__ Out)
{
    extern __shared__ char smem[];
    const uint32_t sb = smem_u32(smem);
    const int tid  = threadIdx.x;
    const int wid  = tid >> 5;
    const int lane = tid & 31;
    const int quad = lane >> 2;
    const int qr   = lane & 3;

    // heavy-first: qtile decreases with blockIdx.z (slowest scheduling dim)
    const int qtile = (NQT - 1) - blockIdx.z;
    const int h     = blockIdx.x;
    const int b     = blockIdx.y;
    const int kh    = h >> 2;
    const int q0    = qtile * BM;
    const int segbase = b * Tseq;

    // ---- prologue: Q -> fp16 hi/lo staged in BUF0 ----
    #pragma unroll
    for (int it = 0; it < 8; it++) {
        int idx = tid + it * NTHREADS;
        int r = idx >> 4, c = idx & 15;
        const float* g = Q + ((size_t)((b * Tseq + q0 + r) * NQH + h)) * Dh + c * 8;
        float4 v0 = *(const float4*)g;
        float4 v1 = *(const float4*)(g + 4);
        float arr[8] = { v0.x, v0.y, v0.z, v0.w, v1.x, v1.y, v1.z, v1.w };
        uint32_t o = toff(r, c);
        cvt_sts8(sb + OFF_BUF0 + o, sb + OFF_BUF0 + KLO_OFF + o, arr);
    }
    __syncthreads();

    // fragment addressing
    const int rA    = 16 * wid + (lane & 15);
    const uint32_t aoff_base = (uint32_t)rA << 8;
    const int aswz   = rA & 7;
    const int achunk = lane >> 4;
    const int brow_l = ((lane >> 4) << 3) + (lane & 7);
    const int bsel   = (lane >> 3) & 1;
    const int bswz   = lane & 7;
    const int vrow_l = lane & 15;
    const int vsel   = lane >> 4;

    // persistent Q hi/lo fragments
    uint32_t Qh[8][4], Ql[8][4];
    #pragma unroll
    for (int k = 0; k < 8; k++) {
        uint32_t ao = aoff_base + ((uint32_t)(((k << 1) + achunk) ^ aswz) << 4);
        ldsm4(Qh[k], sb + OFF_BUF0 + ao);
        ldsm4(Ql[k], sb + OFF_BUF0 + KLO_OFF + ao);
    }
    __syncthreads();   // staging reads done; BUF0 reusable

    // per-thread rows + segment ranges (contiguous sorted segments)
    const int rowl0 = 16 * wid + quad;
    const int row0  = q0 + rowl0;
    const int row1  = row0 + 8;
    const int st0 = seg_start(seg, segbase, row0);
    const int st1 = seg_start(seg, segbase, row1);
    const int wmaxrow = q0 + 16 * wid + 15;        // max q row in this warp

    // active key-tile interval is contiguous: [kt_lo, qtile]
    const int kt_lo = seg_start(seg, segbase, q0) / BN;

    const char* blobs = GKV + ((size_t)(b * NKV + kh) * NQT) * BLOBSZ;
    auto issue_tile = [&](int t, int buf) {
        const char* gsrc = blobs + (size_t)t * BLOBSZ;
        uint32_t sdst = sb + (buf ? OFF_BUF1 : OFF_BUF0);
        #pragma unroll
        for (int it = 0; it < 24; it++) {
            uint32_t off = (uint32_t)tid * 16 + (uint32_t)it * 2048;
            CP16(sdst + off, gsrc + off);
        }
    };

    // pipeline prologue
    issue_tile(kt_lo, 0);
    CP_COMMIT();
    if (kt_lo + 1 <= qtile) issue_tile(kt_lo + 1, 1);
    CP_COMMIT();

    float m0 = MINIT, m1 = MINIT, l0 = 0.0f, l1 = 0.0f;
    float Oa[16][4];
    #pragma unroll
    for (int i = 0; i < 16; i++)
        #pragma unroll
        for (int j = 0; j < 4; j++) Oa[i][j] = 0.0f;

    const float NEG = -__int_as_float(0x7f800000);   // -inf
    const uint32_t ONES2[2] = { 0x3C003C00u, 0x3C003C00u };

    int buf = 0;
    for (int kt = kt_lo; kt <= qtile; kt++, buf ^= 1) {
        const int k0 = kt * BN;
        CP_WAIT1();
        __syncthreads();                           // tile kt resident
        const uint32_t cbase = sb + (buf ? OFF_BUF1 : OFF_BUF0);

        // ---- QK: S = qh*kh + qh*kl + ql*kh (skip blocks above diagonal) ----
        float S[8][4];
        #pragma unroll
        for (int n = 0; n < 8; n++)
            #pragma unroll
            for (int j = 0; j < 4; j++) S[n][j] = 0.0f;

        #pragma unroll
        for (int np = 0; np < 4; np++) {
            if (k0 + np * 16 > wmaxrow) continue;   // warp-uniform causal skip
            #pragma unroll
            for (int k = 0; k < 8; k++) {
                uint32_t bh[4], bl[4];
                uint32_t bo = ((uint32_t)(np * 16 + brow_l) << 8)
                            + ((uint32_t)(((k << 1) + bsel) ^ bswz) << 4);
                ldsm4(bh, cbase + bo);
                ldsm4(bl, cbase + KLO_OFF + bo);
                mma16816(S[2*np],   Qh[k], bh);
                mma16816(S[2*np+1], Qh[k], bh + 2);
                mma16816(S[2*np],   Qh[k], bl);
                mma16816(S[2*np+1], Qh[k], bl + 2);
                mma16816(S[2*np],   Ql[k], bh);
                mma16816(S[2*np+1], Ql[k], bh + 2);
            }
        }

        // ---- masking (range compares) + row max ----
        float mx0 = m0, mx1 = m1;
        #pragma unroll
        for (int n = 0; n < 8; n++) {
            int cg = k0 + n * 8 + qr * 2;
            bool a00 = (cg     >= st0) && (cg     <= row0);
            bool a01 = (cg + 1 >= st0) && (cg + 1 <= row0);
            bool a10 = (cg     >= st1) && (cg     <= row1);
            bool a11 = (cg + 1 >= st1) && (cg + 1 <= row1);
            S[n][0] = a00 ? S[n][0] : NEG;
            S[n][1] = a01 ? S[n][1] : NEG;
            S[n][2] = a10 ? S[n][2] : NEG;
            S[n][3] = a11 ? S[n][3] : NEG;
            mx0 = fmaxf(mx0, fmaxf(S[n][0], S[n][1]));
            mx1 = fmaxf(mx1, fmaxf(S[n][2], S[n][3]));
        }
        mx0 = fmaxf(mx0, __shfl_xor_sync(0xffffffffu, mx0, 1));
        mx0 = fmaxf(mx0, __shfl_xor_sync(0xffffffffu, mx0, 2));
        mx1 = fmaxf(mx1, __shfl_xor_sync(0xffffffffu, mx1, 1));
        mx1 = fmaxf(mx1, __shfl_xor_sync(0xffffffffu, mx1, 2));

        float sc0 = __expf(m0 - mx0);
        float sc1 = __expf(m1 - mx1);
        m0 = mx0; m1 = mx1;

        // ---- exp2 fp16x2 -> P fragments ----
        const float c0 = -mx0 * LOG2E;
        const float c1 = -mx1 * LOG2E;
        uint32_t PH[4][4];
        #pragma unroll
        for (int n = 0; n < 8; n++) {
            float t0 = fmaf(S[n][0], LOG2E, c0);
            float t1 = fmaf(S[n][1], LOG2E, c0);
            float t2 = fmaf(S[n][2], LOG2E, c1);
            float t3 = fmaf(S[n][3], LOG2E, c1);
            uint32_t p01 = ex2_h2(pack_h2(t0, t1));
            uint32_t p23 = ex2_h2(pack_h2(t2, t3));
            PH[n >> 1][(n & 1) << 1]       = p01;
            PH[n >> 1][((n & 1) << 1) | 1] = p23;
        }

        // ---- row sums (ones-MMA) ----
        float Lacc[4] = { 0.0f, 0.0f, 0.0f, 0.0f };
        #pragma unroll
        for (int kc = 0; kc < 4; kc++) {
            if (k0 + kc * 16 > wmaxrow) continue;   // P block provably zero
            mma16816(Lacc, PH[kc], ONES2);
        }
        l0 = l0 * sc0 + Lacc[0];
        l1 = l1 * sc1 + Lacc[2];

        // ---- rescale O ----
        #pragma unroll
        for (int nd = 0; nd < 16; nd++) {
            Oa[nd][0] *= sc0; Oa[nd][1] *= sc0;
            Oa[nd][2] *= sc1; Oa[nd][3] *= sc1;
        }

        // ---- PV (skip zero P blocks) ----
        #pragma unroll
        for (int kc = 0; kc < 4; kc++) {
            if (k0 + kc * 16 > wmaxrow) continue;
            #pragma unroll
            for (int ndp = 0; ndp < 8; ndp++) {
                uint32_t vh[4];
                uint32_t vo = ((uint32_t)(kc * 16 + vrow_l) << 8)
                            + ((uint32_t)((2 * ndp + vsel) ^ bswz) << 4);
                ldsm4t(vh, cbase + VHI_OFF + vo);
                mma16816(Oa[2*ndp],   PH[kc], vh);
                mma16816(Oa[2*ndp+1], PH[kc], vh + 2);
            }
        }

        __syncthreads();                           // buf reads done
        if (kt + 2 <= qtile) issue_tile(kt + 2, buf);
        CP_COMMIT();                               // one group per slot, always
    }

    // ---- epilogue ----
    const float inv0 = 1.0f / l0;
    const float inv1 = 1.0f / l1;
    float* o0 = Out + ((size_t)((b * Tseq + row0) * NQH + h)) * Dh;
    float* o1 = Out + ((size_t)((b * Tseq + row1) * NQH + h)) * Dh;
    #pragma unroll
    for (int nd = 0; nd < 16; nd++) {
        int d = nd * 8 + qr * 2;
        float2 w0 = make_float2(Oa[nd][0] * inv0, Oa[nd][1] * inv0);
        float2 w1 = make_float2(Oa[nd][2] * inv1, Oa[nd][3] * inv1);
        *(float2*)(o0 + d) = w0;
        *(float2*)(o1 + d) = w1;
    }
}

extern "C" void kernel_launch(void* const* d_in, const int* in_sizes, int n_in,
                              void* d_out, int out_size)
{
    const float* Q   = (const float*)d_in[0];
    const float* K   = (const float*)d_in[1];
    const float* V   = (const float*)d_in[2];
    const int*   seg = (const int*)d_in[3];
    float*       O   = (float*)d_out;

    dim3 cg(NQT, NKV, Bsz);
    convert_kv<<<cg, 512>>>(K, V);

    cudaFuncSetAttribute(attn_hmma_kernel,
                         cudaFuncAttributeMaxDynamicSharedMemorySize, SMEM_TOTAL);
    dim3 grid(NQH, Bsz, NQT);
    attn_hmma_kernel<<<grid, NTHREADS, SMEM_TOTAL>>>(Q, seg, O);
}